// round 11
// baseline (speedup 1.0000x reference)
#include <cuda_runtime.h>

// Involution2d: B=8, C=256, G=4, Cpg=64, K=7, H=W=64, pad=3
// out[b,c,ho,wo] = sum_{kh,kw} in[b,c,ho+kh-3,wo+kw-3] * w[b,g,kh,kw,ho,wo] + bias[c]
//
// R10 vs R8 (41.1us): attack per-warp dependency latency
//  - accumulator chains split even/odd rows: 4 f32x2 + 2 scalar independent
//    chains per channel -> critical path 84 -> ~44 cyc
//  - STAGE_CH 2->4, NBUF 4->3 (wait_group 1): half the barriers, ~8-channel
//    lookahead, smem 26.9KB/CTA
//  - geometry/loader/weight residency unchanged (R8 = best known)

#define TILE_W 32
#define TILE_H 8
#define SH 14                    // TILE_H + 6
#define SWP 40                   // smem row stride (floats) = loaded window width
#define PLANE (SH*SWP)           // 560 floats
#define WCHUNK 10                // 16B chunks per row
#define SLOTS (SH*WCHUNK)        // 140
#define STAGE_CH 4
#define CH_PER_CTA 32
#define NSTAGES (CH_PER_CTA/STAGE_CH)   // 8
#define NBUF 3
#define CH_B (PLANE*4)           // 2240 B per channel plane
#define BUF_B (STAGE_CH*CH_B)    // 8960 B per buffer

__device__ __forceinline__ void cpa16(unsigned dst, const float* src) {
    asm volatile("cp.async.cg.shared.global [%0], [%1], 16;\n" :: "r"(dst), "l"(src));
}
__device__ __forceinline__ void cpa_commit() {
    asm volatile("cp.async.commit_group;\n" ::: "memory");
}
__device__ __forceinline__ void cpa_wait1() {
    asm volatile("cp.async.wait_group 1;\n" ::: "memory");
}
__device__ __forceinline__ unsigned long long pack2(float a, float b) {
    unsigned long long r;
    asm("mov.b64 %0, {%1, %2};" : "=l"(r) : "f"(a), "f"(b));
    return r;
}
__device__ __forceinline__ void fma2(unsigned long long& d,
                                     unsigned long long a, unsigned long long b) {
    asm("fma.rn.f32x2 %0, %1, %2, %0;" : "+l"(d) : "l"(a), "l"(b));
}
__device__ __forceinline__ unsigned long long add2(unsigned long long a,
                                                   unsigned long long b) {
    unsigned long long r;
    asm("add.rn.f32x2 %0, %1, %2;" : "=l"(r) : "l"(a), "l"(b));
    return r;
}
__device__ __forceinline__ float hadd2(unsigned long long v) {
    float lo, hi;
    asm("mov.b64 {%0, %1}, %2;" : "=f"(lo), "=f"(hi) : "l"(v));
    return lo + hi;
}

__global__ __launch_bounds__(128, 4)
void involution2d_kernel(const float* __restrict__ input,
                         const float* __restrict__ weight,
                         const float* __restrict__ bias,
                         float* __restrict__ out)
{
    __shared__ __align__(16) float tile[NBUF * STAGE_CH * PLANE];
    __shared__ float sbias[CH_PER_CTA];

    const int tx  = threadIdx.x;            // 0..31
    const int ty  = threadIdx.y;            // 0..3
    const int tid = ty * 32 + tx;

    int bid = blockIdx.x;
    const int half = bid & 1; bid >>= 1;    // channel half
    const int wt = bid & 1;  bid >>= 1;     // 2 tiles across W
    const int ht = bid & 7;  bid >>= 3;     // 8 tiles across H
    const int g  = bid & 3;  bid >>= 2;     // 4 groups
    const int b  = bid;                     // 8 batches

    const int ch0 = half * CH_PER_CTA;
    const int w0g = wt * TILE_W;
    const int h0g = ht * TILE_H;
    const int oy0 = ty * 2;
    const int ho0 = h0g + oy0;
    const int wo  = w0g + tx;

    if (tid < CH_PER_CTA) sbias[tid] = bias[g * 64 + ch0 + tid];

    // ---- compute-side window offsets (window base = w0g-4; tap j -> idx tx+1+j) ----
    const int base  = tx + 1;
    const int p     = base & 1;
    const int jp0   = p;                     // first paired tap
    const int jscal = p ? 0 : 6;             // scalar tap
    const int pairIdx = base + p;            // even -> 8B aligned
    const int scalIdx = base + jscal;

    // ---- weights: 98 regs/thread, parity-dependent pairing, read once ----
    unsigned long long wp0[7][3], wp1[7][3];
    float ws0[7], ws1[7];
    {
        const float* w0 = weight + ((size_t)(b * 4 + g) * 49) * 4096 + ho0 * 64 + wo;
        const float* w1 = w0 + 64;
        #pragma unroll
        for (int r = 0; r < 7; ++r) {
            #pragma unroll
            for (int m = 0; m < 3; ++m) {
                int k = r * 7 + jp0 + 2 * m;
                wp0[r][m] = pack2(w0[k * 4096], w0[(k + 1) * 4096]);
                wp1[r][m] = pack2(w1[k * 4096], w1[(k + 1) * 4096]);
            }
            ws0[r] = w0[(r * 7 + jscal) * 4096];
            ws1[r] = w1[(r * 7 + jscal) * 4096];
        }
    }

    const float* inb  = input + (b * 256 + g * 64 + ch0) * 4096;
    float*       outb = out   + (b * 256 + g * 64 + ch0) * 4096;
    const unsigned sbase = (unsigned)__cvta_generic_to_shared(&tile[0]);

    // ---- loader slots: slot = row*10 + chunk; thread owns tid and tid+128 ----
    int      goffA = 0, goffB = 0;
    unsigned soffA = 0, soffB = 0;
    bool     okA = false, okB = false;
    {
        #pragma unroll
        for (int q = 0; q < 2; ++q) {
            int slot = tid + q * 128;
            if (slot < SLOTS) {
                int row = slot / WCHUNK;
                int ck  = slot - row * WCHUNK;
                int gh  = h0g - 3 + row;
                int gw  = w0g - 4 + 4 * ck;          // chunk fully in or fully out
                bool ok = ((unsigned)gh < 64u) && ((unsigned)gw < 64u);
                int  go = gh * 64 + gw;
                unsigned so = (unsigned)(row * SWP + 4 * ck) * 4u;
                if (q == 0) { goffA = go; soffA = so; okA = ok; }
                else        { goffB = go; soffB = so; okB = ok; }
                if (!ok) {   // halo constant zero across channels: fill all planes once
                    float* z = &tile[(row * SWP + 4 * ck)];
                    #pragma unroll
                    for (int pl = 0; pl < NBUF * STAGE_CH; ++pl) {
                        float4* z4 = (float4*)(z + pl * PLANE);
                        *z4 = make_float4(0.f, 0.f, 0.f, 0.f);
                    }
                }
            }
        }
    }
    const bool hasB = (tid + 128) < SLOTS;

    auto issue = [&](int stage, int bi) {
        const float* gsrc = inb + (size_t)stage * (STAGE_CH * 4096);
        const unsigned bA = sbase + (unsigned)bi * BUF_B;
        #pragma unroll
        for (int c = 0; c < STAGE_CH; ++c) {
            const float* gc = gsrc + c * 4096;
            const unsigned pb = bA + (unsigned)c * CH_B;
            if (okA)         cpa16(pb + soffA, gc + goffA);
            if (hasB && okB) cpa16(pb + soffB, gc + goffB);
        }
    };

    // ---- prologue: stages 0,1 into buffers 0,1 ----
    issue(0, 0); cpa_commit();
    issue(1, 1); cpa_commit();

    int cb = 0;            // buffer holding stage s
    int ib = 2;            // buffer for stage s+2
    for (int s = 0; s < NSTAGES; ++s) {
        cpa_wait1();                 // stage s landed (<=1 group pending)
        __syncthreads();             // buffer ib free; stage s visible to all

        if (s + 2 < NSTAGES) issue(s + 2, ib);
        cpa_commit();                // empty tail groups harmless

        // ---- compute the 4 channels of stage s ----
        const float* bufp = &tile[cb * STAGE_CH * PLANE];
        #pragma unroll
        for (int c = 0; c < STAGE_CH; ++c) {
            const float* plane = bufp + c * PLANE;
            const float bv = sbias[s * STAGE_CH + c];
            // split even/odd-row chains: 4 packed + 2 scalar independent chains
            unsigned long long a0e = 0ull, a0o = 0ull, a1e = 0ull, a1o = 0ull;
            float a0s = bv, a1s = bv;
            #pragma unroll
            for (int r = 0; r < 8; ++r) {
                const float* rowf = plane + (oy0 + r) * SWP;
                const unsigned long long* rp =
                    (const unsigned long long*)(rowf + pairIdx);
                unsigned long long p0 = rp[0], p1 = rp[1], p2 = rp[2];
                float xs = rowf[scalIdx];
                if (r < 7) {
                    unsigned long long& a0 = (r & 1) ? a0o : a0e;
                    fma2(a0, p0, wp0[r][0]);
                    fma2(a0, p1, wp0[r][1]);
                    fma2(a0, p2, wp0[r][2]);
                    a0s = fmaf(xs, ws0[r], a0s);
                }
                if (r >= 1) {
                    unsigned long long& a1 = ((r - 1) & 1) ? a1o : a1e;
                    fma2(a1, p0, wp1[r - 1][0]);
                    fma2(a1, p1, wp1[r - 1][1]);
                    fma2(a1, p2, wp1[r - 1][2]);
                    a1s = fmaf(xs, ws1[r - 1], a1s);
                }
            }
            const int ch = s * STAGE_CH + c;
            float* op = outb + ch * 4096 + ho0 * 64 + wo;
            op[0]  = hadd2(add2(a0e, a0o)) + a0s;
            op[64] = hadd2(add2(a1e, a1o)) + a1s;
        }

        cb = (cb == NBUF - 1) ? 0 : cb + 1;
        ib = (ib == NBUF - 1) ? 0 : ib + 1;
    }
}

extern "C" void kernel_launch(void* const* d_in, const int* in_sizes, int n_in,
                              void* d_out, int out_size)
{
    const float* input  = (const float*)d_in[0];
    const float* weight = (const float*)d_in[1];
    const float* bias   = (const float*)d_in[2];
    float*       out    = (float*)d_out;

    dim3 block(TILE_W, 4, 1);                 // 128 threads
    dim3 grid(8 * 4 * 8 * 2 * 2, 1, 1);       // B*G*Ht*Wt*chhalves = 1024
    involution2d_kernel<<<grid, block>>>(input, weight, bias, out);
}

// round 12
// speedup vs baseline: 1.2194x; 1.2194x over previous
#include <cuda_runtime.h>

// Involution2d: B=8, C=256, G=4, Cpg=64, K=7, H=W=64, pad=3
// out[b,c,ho,wo] = sum_{kh,kw} in[b,c,ho+kh-3,wo+kw-3] * w[b,g,kh,kw,ho,wo] + bias[c]
//
// R11: move to the high-register design point to cut smem-crossbar traffic
//  - 64-thread CTAs, __launch_bounds__(64,4) -> 255 regs/thread, 4 CTAs/SM
//  - TH=4 output rows per thread: 196 weight regs; each 7-wide smem row read
//    feeds 4 accumulators -> 17.5 wf/output (was 28) -> crossbar floor ~15.5us
//  - loader/pipeline/geometry from R8 (best known): 16B cp.async, NBUF=4,
//    wait_group 2, channel-split grid of 1024 CTAs

#define TILE_W 32
#define TILE_H 8
#define TH 4
#define SH 14                    // TILE_H + 6
#define SWP 40                   // smem row stride (floats) = loaded window width
#define PLANE (SH*SWP)           // 560 floats
#define WCHUNK 10                // 16B chunks per row
#define SLOTS (SH*WCHUNK)        // 140
#define STAGE_CH 2
#define CH_PER_CTA 32
#define NSTAGES (CH_PER_CTA/STAGE_CH)   // 16
#define NBUF 4
#define CH_B (PLANE*4)           // 2240 B per channel plane
#define BUF_B (STAGE_CH*CH_B)    // 4480 B per buffer
#define NTHR 64
#define NSLOT 3                  // ceil(140/64)

__device__ __forceinline__ void cpa16(unsigned dst, const float* src) {
    asm volatile("cp.async.cg.shared.global [%0], [%1], 16;\n" :: "r"(dst), "l"(src));
}
__device__ __forceinline__ void cpa_commit() {
    asm volatile("cp.async.commit_group;\n" ::: "memory");
}
__device__ __forceinline__ void cpa_wait2() {
    asm volatile("cp.async.wait_group 2;\n" ::: "memory");
}
__device__ __forceinline__ unsigned long long pack2(float a, float b) {
    unsigned long long r;
    asm("mov.b64 %0, {%1, %2};" : "=l"(r) : "f"(a), "f"(b));
    return r;
}
__device__ __forceinline__ void fma2(unsigned long long& d,
                                     unsigned long long a, unsigned long long b) {
    asm("fma.rn.f32x2 %0, %1, %2, %0;" : "+l"(d) : "l"(a), "l"(b));
}
__device__ __forceinline__ float hadd2(unsigned long long v) {
    float lo, hi;
    asm("mov.b64 {%0, %1}, %2;" : "=f"(lo), "=f"(hi) : "l"(v));
    return lo + hi;
}

__global__ __launch_bounds__(NTHR, 4)
void involution2d_kernel(const float* __restrict__ input,
                         const float* __restrict__ weight,
                         const float* __restrict__ bias,
                         float* __restrict__ out)
{
    __shared__ __align__(16) float tile[NBUF * STAGE_CH * PLANE];
    __shared__ float sbias[CH_PER_CTA];

    const int tx  = threadIdx.x;            // 0..31
    const int ty  = threadIdx.y;            // 0..1
    const int tid = ty * 32 + tx;           // 0..63

    int bid = blockIdx.x;
    const int half = bid & 1; bid >>= 1;    // channel half
    const int wt = bid & 1;  bid >>= 1;     // 2 tiles across W
    const int ht = bid & 7;  bid >>= 3;     // 8 tiles across H
    const int g  = bid & 3;  bid >>= 2;     // 4 groups
    const int b  = bid;                     // 8 batches

    const int ch0 = half * CH_PER_CTA;
    const int w0g = wt * TILE_W;
    const int h0g = ht * TILE_H;
    const int oy0 = ty * TH;                // 0 or 4
    const int ho0 = h0g + oy0;
    const int wo  = w0g + tx;

    if (tid < CH_PER_CTA) sbias[tid] = bias[g * 64 + ch0 + tid];

    // ---- compute-side window offsets (window base = w0g-4; tap j -> idx tx+1+j) ----
    const int base  = tx + 1;
    const int p     = base & 1;
    const int jp0   = p;                     // first paired tap
    const int jscal = p ? 0 : 6;             // scalar tap
    const int pairIdx = base + p;            // even -> 8B aligned
    const int scalIdx = base + jscal;

    // ---- weights: 4 rows x 49 = 196 regs/thread, parity pairing, read once ----
    unsigned long long wp[TH][7][3];
    float ws[TH][7];
    {
        const float* wb = weight + ((size_t)(b * 4 + g) * 49) * 4096 + ho0 * 64 + wo;
        #pragma unroll
        for (int t = 0; t < TH; ++t) {
            const float* wt_ = wb + t * 64;
            #pragma unroll
            for (int r = 0; r < 7; ++r) {
                #pragma unroll
                for (int m = 0; m < 3; ++m) {
                    int k = r * 7 + jp0 + 2 * m;
                    wp[t][r][m] = pack2(wt_[k * 4096], wt_[(k + 1) * 4096]);
                }
                ws[t][r] = wt_[(r * 7 + jscal) * 4096];
            }
        }
    }

    const float* inb  = input + (b * 256 + g * 64 + ch0) * 4096;
    float*       outb = out   + (b * 256 + g * 64 + ch0) * 4096;
    const unsigned sbase = (unsigned)__cvta_generic_to_shared(&tile[0]);

    // ---- loader slots: slot = row*10 + chunk; thread owns tid + q*64, q=0..2 ----
    int      goff[NSLOT];
    unsigned soff[NSLOT];
    bool     okm [NSLOT];
    #pragma unroll
    for (int q = 0; q < NSLOT; ++q) {
        int slot = tid + q * NTHR;
        okm[q] = false; goff[q] = 0; soff[q] = 0;
        if (slot < SLOTS) {
            int row = slot / WCHUNK;
            int ck  = slot - row * WCHUNK;
            int gh  = h0g - 3 + row;
            int gw  = w0g - 4 + 4 * ck;          // chunk fully in or fully out
            bool ok = ((unsigned)gh < 64u) && ((unsigned)gw < 64u);
            okm [q] = ok;
            goff[q] = gh * 64 + gw;
            soff[q] = (unsigned)(row * SWP + 4 * ck) * 4u;
            if (!ok) {   // halo constant zero across channels: fill all planes once
                float* z = &tile[(row * SWP + 4 * ck)];
                #pragma unroll
                for (int pl = 0; pl < NBUF * STAGE_CH; ++pl) {
                    float4* z4 = (float4*)(z + pl * PLANE);
                    *z4 = make_float4(0.f, 0.f, 0.f, 0.f);
                }
            }
        }
    }

    auto issue = [&](int stage, int bi) {
        const float* gsrc = inb + (size_t)stage * (STAGE_CH * 4096);
        const unsigned bA = sbase + (unsigned)bi * BUF_B;
        #pragma unroll
        for (int c = 0; c < STAGE_CH; ++c) {
            const float* gc = gsrc + c * 4096;
            const unsigned pb = bA + (unsigned)c * CH_B;
            #pragma unroll
            for (int q = 0; q < NSLOT; ++q)
                if (okm[q]) cpa16(pb + soff[q], gc + goff[q]);
        }
    };

    // ---- prologue: stages 0..2 into buffers 0..2 ----
    issue(0, 0); cpa_commit();
    issue(1, 1); cpa_commit();
    issue(2, 2); cpa_commit();

    int cb = 0;            // buffer holding stage s
    int ib = 3;            // buffer for stage s+3
    for (int s = 0; s < NSTAGES; ++s) {
        cpa_wait2();                 // stage s landed (<=2 groups pending)
        __syncthreads();             // buffer ib free; stage s visible (2 warps)

        if (s + 3 < NSTAGES) issue(s + 3, ib);
        cpa_commit();                // empty tail groups harmless

        // ---- compute the 2 channels of stage s, 4 output rows each ----
        const float* bufp = &tile[cb * STAGE_CH * PLANE];
        #pragma unroll
        for (int c = 0; c < STAGE_CH; ++c) {
            const float* plane = bufp + c * PLANE;
            const float bv = sbias[s * STAGE_CH + c];
            unsigned long long acc[TH];
            float accs[TH];
            #pragma unroll
            for (int t = 0; t < TH; ++t) { acc[t] = 0ull; accs[t] = bv; }

            #pragma unroll
            for (int r = 0; r < TH + 6; ++r) {       // 10 input rows
                const float* rowf = plane + (oy0 + r) * SWP;
                const unsigned long long* rp =
                    (const unsigned long long*)(rowf + pairIdx);
                unsigned long long p0 = rp[0], p1 = rp[1], p2 = rp[2];
                float xs = rowf[scalIdx];
                #pragma unroll
                for (int t = 0; t < TH; ++t) {
                    if (r >= t && r <= t + 6) {      // compile-time per (r,t)
                        const int kr = r - t;
                        fma2(acc[t], p0, wp[t][kr][0]);
                        fma2(acc[t], p1, wp[t][kr][1]);
                        fma2(acc[t], p2, wp[t][kr][2]);
                        accs[t] = fmaf(xs, ws[t][kr], accs[t]);
                    }
                }
            }
            const int ch = s * STAGE_CH + c;
            float* op = outb + ch * 4096 + ho0 * 64 + wo;
            #pragma unroll
            for (int t = 0; t < TH; ++t)
                op[t * 64] = hadd2(acc[t]) + accs[t];
        }

        cb = (cb == NBUF - 1) ? 0 : cb + 1;
        ib = (ib == NBUF - 1) ? 0 : ib + 1;
    }
}

extern "C" void kernel_launch(void* const* d_in, const int* in_sizes, int n_in,
                              void* d_out, int out_size)
{
    const float* input  = (const float*)d_in[0];
    const float* weight = (const float*)d_in[1];
    const float* bias   = (const float*)d_in[2];
    float*       out    = (float*)d_out;

    dim3 block(TILE_W, 2, 1);                 // 64 threads
    dim3 grid(8 * 4 * 8 * 2 * 2, 1, 1);       // B*G*Ht*Wt*chhalves = 1024
    involution2d_kernel<<<grid, block>>>(input, weight, bias, out);
}